// round 7
// baseline (speedup 1.0000x reference)
#include <cuda_runtime.h>

// FINAL FORM — confirmation re-bench of the best configuration.
//
// Reference analysis (verified rel_err == 0.0 across R1-R6):
//   The reference ends with softmax(d, axis=-1) where d has last dim == 1.
//   Softmax over a size-1 axis is identically 1.0, so
//   out[b,t] = sigmoid(1.0) = 0.7310585786300049 for every (b,t),
//   independent of all inputs. Output is a constant (64, 512) fp32 tensor.
//
// Session evidence:
//   kernel-node graphs (4 structurally different fills): 4.61-4.83us
//   memcpy-node graph (this form, R6):                   4.576us  <- best
// The graph has a single copy-engine memcpy node (ncu saw zero kernel
// launches); source is a 128KB statically-initialized __device__ table
// (populated at module load, outside timing; no allocation anywhere).

static constexpr float SIGMOID_ONE = 0.73105857863000487925f; // 1/(1+exp(-1))

#define V1    SIGMOID_ONE
#define V8    V1,V1,V1,V1,V1,V1,V1,V1
#define V64   V8,V8,V8,V8,V8,V8,V8,V8
#define V512  V64,V64,V64,V64,V64,V64,V64,V64
#define V4096 V512,V512,V512,V512,V512,V512,V512,V512

// 32768 floats = 128 KB of static device data, initialized at module load.
__device__ float g_const_out[32768] = {
    V4096, V4096, V4096, V4096, V4096, V4096, V4096, V4096
};

// Fallback fill kernel (only used if symbol lookup fails; never expected).
__global__ void __launch_bounds__(128, 1)
AttentionRNNLayer_87677462380995_kernel(float4* __restrict__ out4, int n4) {
    int i = blockIdx.x * blockDim.x + threadIdx.x;
    if (i < n4) {
        out4[i] = make_float4(SIGMOID_ONE, SIGMOID_ONE, SIGMOID_ONE, SIGMOID_ONE);
    }
}

extern "C" void kernel_launch(void* const* d_in, const int* in_sizes, int n_in,
                              void* d_out, int out_size) {
    (void)d_in; (void)in_sizes; (void)n_in;
    void* src = nullptr;
    cudaError_t e = cudaGetSymbolAddress(&src, g_const_out);
    if (e == cudaSuccess && src != nullptr) {
        // Single D2D memcpy node in the captured graph (copy-engine path).
        cudaMemcpyAsync(d_out, src, (size_t)out_size * sizeof(float),
                        cudaMemcpyDeviceToDevice, 0);
    } else {
        int n4 = out_size >> 2;
        int threads = 128;
        int blocks = (n4 + threads - 1) / threads;
        AttentionRNNLayer_87677462380995_kernel<<<blocks, threads>>>(
            reinterpret_cast<float4*>(d_out), n4);
    }
}

// round 8
// speedup vs baseline: 1.1944x; 1.1944x over previous
#include <cuda_runtime.h>

// FINAL KERNEL — reverted to the kernel-node form after the memcpy-node
// experiment failed its confirmation re-bench.
//
// Reference analysis (verified rel_err == 0.0 across R1-R7):
//   The reference ends with softmax(d, axis=-1) where d has last dim == 1.
//   Softmax over a size-1 axis is identically 1.0, so
//   out[b,t] = sigmoid(1.0) = 0.7310585786300049 for every (b,t),
//   independent of all inputs. Output is a constant (64, 512) fp32 tensor.
//
// Session evidence (bench dur_us):
//   kernel-node graphs (5 runs, 4 variants): 4.608-4.832  (tight, mean ~4.77)
//   memcpy-node graph (2 runs):              4.576, 5.504 (wide, mean ~5.04)
// The copy-engine path has worse mean and ~4x the variance; the single-kernel
// graph is the floor. Kernel dur ~3.6us is pure launch overhead (issue <= 4%,
// DRAM 0.0%); nothing in the body is on the critical path.

static constexpr float SIGMOID_ONE = 0.73105857863000487925f; // 1/(1+exp(-1))

__global__ void __launch_bounds__(128, 1)
AttentionRNNLayer_87677462380995_kernel(float4* __restrict__ out4, int n4) {
    int i = blockIdx.x * blockDim.x + threadIdx.x;
    if (i < n4) {
        out4[i] = make_float4(SIGMOID_ONE, SIGMOID_ONE, SIGMOID_ONE, SIGMOID_ONE);
    }
}

extern "C" void kernel_launch(void* const* d_in, const int* in_sizes, int n_in,
                              void* d_out, int out_size) {
    (void)d_in; (void)in_sizes; (void)n_in;
    // out_size = 32768 fp32 = 8192 float4 stores; one coalesced STG.128 per thread.
    int n4 = out_size >> 2;                     // 8192
    int threads = 128;
    int blocks = (n4 + threads - 1) / threads;  // 64
    AttentionRNNLayer_87677462380995_kernel<<<blocks, threads>>>(
        reinterpret_cast<float4*>(d_out), n4);
}